// round 10
// baseline (speedup 1.0000x reference)
#include <cuda_runtime.h>
#include <cooperative_groups.h>
#include <math.h>
#include <stdint.h>

namespace cg = cooperative_groups;

// ---------------------------------------------------------------------------
// LogNCDE depth-2 log-ODE scan, 4-CTA cluster per batch element (128 CTAs).
// Rank r owns channels {2r,2r+1} and Wv2 rows [128r,128r+128).
// v10: in-warp K-split — thread t owns output o=t>>1, k-half kh=t&1, with
// half-row weight tiles in registers (f32x2). Each matvec = reg dot +
// one shfl_xor(1) + direct write by the even lane. No smem partial trees;
// 7 barriers + 2 cluster.syncs per step. Prep kernel computes sigs + h0.
// ---------------------------------------------------------------------------

namespace {
constexpr int kB   = 32;
constexpr int kT   = 2049;
constexpr int kD   = 8;
constexpr int kS   = 64;
constexpr int kH   = 128;
constexpr int kP   = 28;
constexpr int kNW  = 128;
constexpr int kWin = 16;
constexpr int kOut = 8;
constexpr int CL   = 4;
constexpr int NT   = 256;

// shared-memory float offsets (16B aligned)
constexpr int OFF_SIGS  = 0;        // [128][36]
constexpr int OFF_CH    = 4608;     // [128][16]
constexpr int OFF_BV0   = 6656;     // 128
constexpr int OFF_BV1   = 6784;     // 128
constexpr int OFF_BV2S  = 6912;     // 128
constexpr int OFF_WR    = 7040;     // 512
constexpr int OFF_BR    = 7552;     // 16
constexpr int OFF_HH    = 7568;     // [129][64]
constexpr int OFF_Z0    = 15824;    // 128
constexpr int OFF_D0    = 15952;    // 128
constexpr int OFF_Z1    = 16080;    // 128
constexpr int OFF_D1    = 16208;    // 128
constexpr int OFF_V     = 16336;    // 512 (single buffer)
constexpr int OFF_TDS   = 16848;    // 128
constexpr int OFF_WT    = 16976;    // 2 x 64
constexpr int OFF_PT    = 17104;    // 2 x 128
constexpr int OFF_UT    = 17360;    // 2 x 128
constexpr int OFF_RD    = 17616;    // 128
constexpr int OFF_RSLOT = 17744;    // 4 x 64
constexpr int SMEMF     = 18000;    // 72 KB
}  // namespace

__device__ float g_sigs[kB * kNW * 36];   // per-batch window signatures
__device__ float g_h0[kB * kS];           // per-batch initial state

static __device__ const int c_II[kP] =
    {0,0,0,0,0,0,0,1,1,1,1,1,1,2,2,2,2,2,3,3,3,3,4,4,4,5,5,6};
static __device__ const int c_JJ[kP] =
    {1,2,3,4,5,6,7,2,3,4,5,6,7,3,4,5,6,7,4,5,6,7,5,6,7,6,7,7};

using u64t = unsigned long long;

__device__ __forceinline__ int pidx(int i, int j) {   // Lyndon pair index, i<j
    return 7 * i - (i * (i - 1)) / 2 + (j - i - 1);
}
__device__ __forceinline__ u64t ffma2(u64t a, u64t b, u64t c) {
    u64t r;
    asm("fma.rn.f32x2 %0, %1, %2, %3;" : "=l"(r) : "l"(a), "l"(b), "l"(c));
    return r;
}
__device__ __forceinline__ float fold2(u64t a) {
    float lo, hi;
    asm("mov.b64 {%0, %1}, %2;" : "=f"(lo), "=f"(hi) : "l"(a));
    return lo + hi;
}
__device__ __forceinline__ float tanh_ap(float x) {
    float r; asm("tanh.approx.f32 %0, %1;" : "=f"(r) : "f"(x)); return r;
}
__device__ __forceinline__ void sp_sg(float s, float& z, float& d) {
    if (s > 20.f) { z = s; d = 1.f; }
    else {
        float e = __expf(s);
        float inv = __frcp_rn(1.f + e);
        z = __logf(1.f + e);
        d = e * inv;
    }
}
__device__ __forceinline__ float sp_f(float x) {   // accurate (one-time h0)
    return (x > 20.f) ? x : log1pf(expf(x));
}

// ======================= prep kernel: signatures + h0 =======================
__global__ __launch_bounds__(128, 1)
void logncde_prep_kernel(
    const float* __restrict__ x,
    const float* __restrict__ Wi0, const float* __restrict__ bi0,
    const float* __restrict__ Wi1, const float* __restrict__ bi1,
    const float* __restrict__ Wi2, const float* __restrict__ bi2)
{
    __shared__ float z0[kH], z1[kH];
    const int b = blockIdx.x;
    const int t = threadIdx.x;

    // depth-2 log-signature, one window per thread
    {
        const float* xb = x + (size_t)b * kT * kD + (size_t)t * kWin * kD;
        float cum[kD], prev[kD], Mm[kD * kD];
        #pragma unroll
        for (int i = 0; i < kD; i++) { cum[i] = 0.f; prev[i] = xb[i]; }
        #pragma unroll
        for (int i = 0; i < kD * kD; i++) Mm[i] = 0.f;
        for (int w = 0; w < kWin; w++) {
            float dl[kD];
            #pragma unroll
            for (int j = 0; j < kD; j++) {
                float c = xb[(w + 1) * kD + j];
                dl[j] = c - prev[j];
                prev[j] = c;
            }
            #pragma unroll
            for (int i = 0; i < kD; i++)
                #pragma unroll
                for (int j = 0; j < kD; j++)
                    Mm[i * kD + j] = fmaf(cum[i], dl[j], Mm[i * kD + j]);
            #pragma unroll
            for (int i = 0; i < kD; i++) cum[i] += dl[i];
        }
        float* sgw = &g_sigs[((size_t)b * kNW + t) * 36];
        #pragma unroll
        for (int i = 0; i < kD; i++) sgw[i] = cum[i];
        #pragma unroll
        for (int p = 0; p < kP; p++) {
            int i = c_II[p], j = c_JJ[p];
            sgw[8 + p] = 0.5f * (Mm[i * kD + j] - Mm[j * kD + i]);
        }
    }

    // initial MLP h0 (accurate path)
    const float* x0 = x + (size_t)b * kT * kD;
    {
        float acc = bi0[t];
        #pragma unroll
        for (int k = 0; k < kD; k++) acc = fmaf(Wi0[t * kD + k], x0[k], acc);
        z0[t] = sp_f(acc);
    }
    __syncthreads();
    {
        float acc = bi1[t];
        #pragma unroll 16
        for (int k = 0; k < kH; k++) acc = fmaf(Wi1[t * kH + k], z0[k], acc);
        z1[t] = sp_f(acc);
    }
    __syncthreads();
    if (t < kS) {
        float acc = bi2[t];
        #pragma unroll 16
        for (int k = 0; k < kH; k++) acc = fmaf(Wi2[t * kH + k], z1[k], acc);
        g_h0[b * kS + t] = acc;
    }
}

// ============================== scan kernel ================================
__global__ __launch_bounds__(NT, 1) __cluster_dims__(CL, 1, 1)
void logncde_v10_kernel(
    const float* __restrict__ Wv0, const float* __restrict__ bv0,
    const float* __restrict__ Wv1, const float* __restrict__ bv1,
    const float* __restrict__ Wv2, const float* __restrict__ bv2,
    const float* __restrict__ Wr,  const float* __restrict__ br,
    float* __restrict__ out)
{
    extern __shared__ float sm[];
    cg::cluster_group cluster = cg::this_cluster();
    const int t    = threadIdx.x;
    const int rank = (int)cluster.block_rank();
    const int b    = blockIdx.x >> 2;
    const int d0g  = 2 * rank;
    const int o    = t >> 1;     // owned output row (0..127)
    const int kh   = t & 1;      // k-half

    float* peer[CL - 1];
    #pragma unroll
    for (int p = 1; p < CL; p++)
        peer[p - 1] = cluster.map_shared_rank(sm, (rank + p) & (CL - 1));

    // ---- register half-row weight tiles as packed f32x2 ----
    // w0: Wv0 row o, k in [kh*32, kh*32+32)  -> 16 u64
    // w1: Wv1 row o, k in [kh*64, kh*64+64)  -> 32 u64
    // w2: Wv2 row (128*rank+o), k-half       -> 32 u64
    u64t w0[16], w1[32], w2[32];
    {
        const ulonglong2* W0 = (const ulonglong2*)Wv0;   // row = 16 ull2
        #pragma unroll
        for (int j = 0; j < 8; j++) {
            ulonglong2 v = W0[o * 16 + kh * 8 + j];
            w0[2 * j] = v.x; w0[2 * j + 1] = v.y;
        }
        const ulonglong2* W1 = (const ulonglong2*)Wv1;   // row = 32 ull2
        #pragma unroll
        for (int j = 0; j < 16; j++) {
            ulonglong2 v = W1[o * 32 + kh * 16 + j];
            w1[2 * j] = v.x; w1[2 * j + 1] = v.y;
        }
        const ulonglong2* W2 = (const ulonglong2*)Wv2;   // row = 32 ull2
        #pragma unroll
        for (int j = 0; j < 16; j++) {
            ulonglong2 v = W2[(kH * rank + o) * 32 + kh * 16 + j];
            w2[2 * j] = v.x; w2[2 * j + 1] = v.y;
        }
    }

    // ---- staging ----
    for (int i = t; i < kH; i += NT) {
        sm[OFF_BV0 + i]  = bv0[i];
        sm[OFF_BV1 + i]  = bv1[i];
        sm[OFF_BV2S + i] = bv2[kH * rank + i];
    }
    for (int i = t; i < kOut * kS; i += NT) sm[OFF_WR + i] = Wr[i];
    if (t < kOut) sm[OFF_BR + t] = br[t];
    {
        const float* src = &g_sigs[(size_t)b * kNW * 36];
        for (int i = t; i < kNW * 36; i += NT) sm[OFF_SIGS + i] = src[i];
    }
    if (t < kS) sm[OFF_HH + t] = g_h0[b * kS + t];
    __syncthreads();

    // ---- precompute C coefficients for all steps (this rank's 2 channels) ----
    for (int i = t; i < kNW * 16; i += NT) {
        int n = i >> 4, j = i & 15;
        int dl = j >> 3, e = j & 7;
        int d = d0g + dl;
        const float* sgn = &sm[OFF_SIGS + n * 36];
        float v = 0.f;
        if (e < d)      v =  sgn[8 + pidx(e, d)];
        else if (e > d) v = -sgn[8 + pidx(d, e)];
        sm[OFF_CH + n * 16 + dl * 8 + e] = v;
    }

    cluster.sync();

    // ============================ scan loop ============================
    for (int n = 0; n < kNW; n++) {

        // --- A: z0[o] = sp(Wv0 h + bv0)  (reg dot + shfl + direct write)
        {
            const ulonglong2* h2 = (const ulonglong2*)&sm[OFF_HH + n * kS];
            u64t a0 = 0, a1 = 0, a2 = 0, a3 = 0;
            #pragma unroll
            for (int j = 0; j < 4; j++) {
                ulonglong2 v0 = h2[kh * 8 + 2 * j];
                ulonglong2 v1 = h2[kh * 8 + 2 * j + 1];
                a0 = ffma2(w0[4 * j],     v0.x, a0);
                a1 = ffma2(w0[4 * j + 1], v0.y, a1);
                a2 = ffma2(w0[4 * j + 2], v1.x, a2);
                a3 = ffma2(w0[4 * j + 3], v1.y, a3);
            }
            float s = (fold2(a0) + fold2(a1)) + (fold2(a2) + fold2(a3));
            s += __shfl_xor_sync(0xffffffffu, s, 1);
            if (kh == 0) {
                float z, d;
                sp_sg(s + sm[OFF_BV0 + o], z, d);
                sm[OFF_Z0 + o] = z;
                sm[OFF_D0 + o] = d;
            }
        }
        __syncthreads();

        // --- B: z1[o] = sp(Wv1 z0 + bv1)
        {
            const ulonglong2* z2 = (const ulonglong2*)&sm[OFF_Z0];
            u64t a0 = 0, a1 = 0, a2 = 0, a3 = 0;
            #pragma unroll
            for (int j = 0; j < 8; j++) {
                ulonglong2 v0 = z2[kh * 16 + 2 * j];
                ulonglong2 v1 = z2[kh * 16 + 2 * j + 1];
                a0 = ffma2(w1[4 * j],     v0.x, a0);
                a1 = ffma2(w1[4 * j + 1], v0.y, a1);
                a2 = ffma2(w1[4 * j + 2], v1.x, a2);
                a3 = ffma2(w1[4 * j + 3], v1.y, a3);
            }
            float s = (fold2(a0) + fold2(a1)) + (fold2(a2) + fold2(a3));
            s += __shfl_xor_sync(0xffffffffu, s, 1);
            if (kh == 0) {
                float z, d;
                sp_sg(s + sm[OFF_BV1 + o], z, d);
                sm[OFF_Z1 + o] = z;
                sm[OFF_D1 + o] = d;
            }
        }
        __syncthreads();

        // --- C: V[128r+o] = tanh(Wv2s z1 + bv2s), push slice to peers
        {
            const ulonglong2* z2 = (const ulonglong2*)&sm[OFF_Z1];
            u64t a0 = 0, a1 = 0, a2 = 0, a3 = 0;
            #pragma unroll
            for (int j = 0; j < 8; j++) {
                ulonglong2 v0 = z2[kh * 16 + 2 * j];
                ulonglong2 v1 = z2[kh * 16 + 2 * j + 1];
                a0 = ffma2(w2[4 * j],     v0.x, a0);
                a1 = ffma2(w2[4 * j + 1], v0.y, a1);
                a2 = ffma2(w2[4 * j + 2], v1.x, a2);
                a3 = ffma2(w2[4 * j + 3], v1.y, a3);
            }
            float s = (fold2(a0) + fold2(a1)) + (fold2(a2) + fold2(a3));
            s += __shfl_xor_sync(0xffffffffu, s, 1);
            if (kh == 0) {
                float v = tanh_ap(s + sm[OFF_BV2S + o]);
                int vi = OFF_V + kH * rank + o;
                sm[vi] = v;
                sm[OFF_TDS + o] = 1.f - v * v;
                peer[0][vi] = v;
                peer[1][vi] = v;
                peer[2][vi] = v;
            }
        }
        cluster.sync();   // V(n) gathered everywhere

        // --- D: tangents w_dl = sum_e C[dl,e] V_e (own 2 channels)
        if (t < kH) {
            int dl = t >> 6, a_ = t & 63;
            const float* cj = &sm[OFF_CH + n * 16 + dl * 8];
            float acc = 0.f;
            #pragma unroll
            for (int e = 0; e < kD; e++)
                acc = fmaf(cj[e], sm[OFF_V + e * kS + a_], acc);
            sm[OFF_WT + dl * kS + a_] = acc;
        }
        __syncthreads();

        // --- E: pt_c[o] = D0[o] * (Wv0 wt_c)[o], both channels
        {
            const ulonglong2* wt2 = (const ulonglong2*)&sm[OFF_WT];
            u64t a0 = 0, a1 = 0, a2 = 0, a3 = 0;
            u64t b0 = 0, b1 = 0, b2 = 0, b3 = 0;
            #pragma unroll
            for (int j = 0; j < 4; j++) {
                ulonglong2 v0 = wt2[kh * 8 + 2 * j];
                ulonglong2 v1 = wt2[kh * 8 + 2 * j + 1];
                ulonglong2 u0 = wt2[16 + kh * 8 + 2 * j];
                ulonglong2 u1 = wt2[16 + kh * 8 + 2 * j + 1];
                a0 = ffma2(w0[4 * j],     v0.x, a0);
                a1 = ffma2(w0[4 * j + 1], v0.y, a1);
                a2 = ffma2(w0[4 * j + 2], v1.x, a2);
                a3 = ffma2(w0[4 * j + 3], v1.y, a3);
                b0 = ffma2(w0[4 * j],     u0.x, b0);
                b1 = ffma2(w0[4 * j + 1], u0.y, b1);
                b2 = ffma2(w0[4 * j + 2], u1.x, b2);
                b3 = ffma2(w0[4 * j + 3], u1.y, b3);
            }
            float s0 = (fold2(a0) + fold2(a1)) + (fold2(a2) + fold2(a3));
            float s1 = (fold2(b0) + fold2(b1)) + (fold2(b2) + fold2(b3));
            s0 += __shfl_xor_sync(0xffffffffu, s0, 1);
            s1 += __shfl_xor_sync(0xffffffffu, s1, 1);
            if (kh == 0) {
                float d0v = sm[OFF_D0 + o];
                sm[OFF_PT + o]       = s0 * d0v;
                sm[OFF_PT + kH + o]  = s1 * d0v;
            }
        }
        __syncthreads();

        // --- F: ut_c[o] = D1[o] * (Wv1 pt_c)[o], both channels
        {
            const ulonglong2* p2 = (const ulonglong2*)&sm[OFF_PT];
            u64t a0 = 0, a1 = 0, a2 = 0, a3 = 0;
            u64t b0 = 0, b1 = 0, b2 = 0, b3 = 0;
            #pragma unroll
            for (int j = 0; j < 8; j++) {
                ulonglong2 v0 = p2[kh * 16 + 2 * j];
                ulonglong2 v1 = p2[kh * 16 + 2 * j + 1];
                ulonglong2 u0 = p2[32 + kh * 16 + 2 * j];
                ulonglong2 u1 = p2[32 + kh * 16 + 2 * j + 1];
                a0 = ffma2(w1[4 * j],     v0.x, a0);
                a1 = ffma2(w1[4 * j + 1], v0.y, a1);
                a2 = ffma2(w1[4 * j + 2], v1.x, a2);
                a3 = ffma2(w1[4 * j + 3], v1.y, a3);
                b0 = ffma2(w1[4 * j],     u0.x, b0);
                b1 = ffma2(w1[4 * j + 1], u0.y, b1);
                b2 = ffma2(w1[4 * j + 2], u1.x, b2);
                b3 = ffma2(w1[4 * j + 3], u1.y, b3);
            }
            float s0 = (fold2(a0) + fold2(a1)) + (fold2(a2) + fold2(a3));
            float s1 = (fold2(b0) + fold2(b1)) + (fold2(b2) + fold2(b3));
            s0 += __shfl_xor_sync(0xffffffffu, s0, 1);
            s1 += __shfl_xor_sync(0xffffffffu, s1, 1);
            if (kh == 0) {
                float d1v = sm[OFF_D1 + o];
                sm[OFF_UT + o]      = s0 * d1v;
                sm[OFF_UT + kH + o] = s1 * d1v;
            }
        }
        __syncthreads();

        // --- G: rd[o] = TDS[o] * (Wv2s ut_{channel(o)})[o]
        {
            const ulonglong2* u2 =
                (const ulonglong2*)&sm[OFF_UT + (o >> 6) * kH];
            u64t a0 = 0, a1 = 0, a2 = 0, a3 = 0;
            #pragma unroll
            for (int j = 0; j < 8; j++) {
                ulonglong2 v0 = u2[kh * 16 + 2 * j];
                ulonglong2 v1 = u2[kh * 16 + 2 * j + 1];
                a0 = ffma2(w2[4 * j],     v0.x, a0);
                a1 = ffma2(w2[4 * j + 1], v0.y, a1);
                a2 = ffma2(w2[4 * j + 2], v1.x, a2);
                a3 = ffma2(w2[4 * j + 3], v1.y, a3);
            }
            float s = (fold2(a0) + fold2(a1)) + (fold2(a2) + fold2(a3));
            s += __shfl_xor_sync(0xffffffffu, s, 1);
            if (kh == 0)
                sm[OFF_RD + o] = s * sm[OFF_TDS + o];
        }
        __syncthreads();

        // --- fold: correction c = rd folded + a.V(own channels); push
        if (t < kS) {
            const float* sgn = &sm[OFF_SIGS + n * 36];
            float rs = sm[OFF_RD + t] + sm[OFF_RD + kS + t]
                     + sgn[d0g]     * sm[OFF_V + d0g * kS + t]
                     + sgn[d0g + 1] * sm[OFF_V + (d0g + 1) * kS + t];
            int ri = OFF_RSLOT + kS * rank + t;
            sm[ri] = rs;
            peer[0][ri] = rs;
            peer[1][ri] = rs;
            peer[2][ri] = rs;
        }
        cluster.sync();   // corrections gathered everywhere

        // --- H: h_{n+1} = h_n + sum_p c_p
        if (t < kS) {
            float acc = sm[OFF_HH + n * kS + t];
            #pragma unroll
            for (int p = 0; p < CL; p++)
                acc += sm[OFF_RSLOT + p * kS + t];
            sm[OFF_HH + (n + 1) * kS + t] = acc;
        }
        __syncthreads();
    }

    // ---- readout of the full h history (rank 0, parallel GEMM) ----
    if (rank == 0) {
        for (int idx = t; idx < (kNW + 1) * kOut; idx += NT) {
            int n = idx >> 3, oo = idx & 7;
            float acc = sm[OFF_BR + oo];
            const float* hh = &sm[OFF_HH + n * kS];
            #pragma unroll 16
            for (int a = 0; a < kS; a++)
                acc = fmaf(sm[OFF_WR + oo * kS + a], hh[a], acc);
            out[((size_t)b * (kNW + 1) + n) * kOut + oo] = acc;
        }
    }
    cluster.sync();   // no CTA exits while peers may still touch its smem
}

extern "C" void kernel_launch(void* const* d_in, const int* in_sizes, int n_in,
                              void* d_out, int out_size) {
    // metadata order: ts, x, Wi0,bi0, Wi1,bi1, Wi2,bi2, Wv0,bv0, Wv1,bv1, Wv2,bv2, Wr,br
    const float* x   = (const float*)d_in[1];
    const float* Wi0 = (const float*)d_in[2];
    const float* bi0 = (const float*)d_in[3];
    const float* Wi1 = (const float*)d_in[4];
    const float* bi1 = (const float*)d_in[5];
    const float* Wi2 = (const float*)d_in[6];
    const float* bi2 = (const float*)d_in[7];
    const float* Wv0 = (const float*)d_in[8];
    const float* bv0 = (const float*)d_in[9];
    const float* Wv1 = (const float*)d_in[10];
    const float* bv1 = (const float*)d_in[11];
    const float* Wv2 = (const float*)d_in[12];
    const float* bv2 = (const float*)d_in[13];
    const float* Wr  = (const float*)d_in[14];
    const float* br  = (const float*)d_in[15];
    float* out = (float*)d_out;

    logncde_prep_kernel<<<kB, 128>>>(x, Wi0, bi0, Wi1, bi1, Wi2, bi2);

    cudaFuncSetAttribute(logncde_v10_kernel,
                         cudaFuncAttributeMaxDynamicSharedMemorySize,
                         SMEMF * (int)sizeof(float));
    logncde_v10_kernel<<<kB * CL, NT, SMEMF * sizeof(float)>>>(
        Wv0, bv0, Wv1, bv1, Wv2, bv2, Wr, br, out);
}